// round 1
// baseline (speedup 1.0000x reference)
#include <cuda_runtime.h>
#include <math.h>

#define BATCH   8
#define CCH     512
#define NHEADS  8
#define DHEAD   64
#define NTOK    1024
#define NGROUP  32
#define CPG     16      // channels per group
#define GN_ELEMS (CPG * NTOK)   // 16384 elements per (b, group)

// ---------------- scratch (alloc-free: __device__ globals) ----------------
__device__ float g_xn[BATCH * CCH * NTOK];            // groupnorm output [b, c, n]
__device__ float g_q [BATCH * NHEADS * NTOK * DHEAD]; // [b, h, n, d]
__device__ float g_k [BATCH * NHEADS * NTOK * DHEAD];
__device__ float g_v [BATCH * NHEADS * NTOK * DHEAD];
__device__ float g_ao[BATCH * CCH * NTOK];            // attention out [b, c, n]

// ===========================================================================
// Kernel 1: GroupNorm. grid = 256 blocks (b*32+g), 256 threads.
// ===========================================================================
__global__ void __launch_bounds__(256) groupnorm_kernel(
    const float* __restrict__ x,
    const float* __restrict__ gw,
    const float* __restrict__ gb)
{
    const int b = blockIdx.x >> 5;
    const int g = blockIdx.x & 31;
    const int tid = threadIdx.x;
    const float* xp = x + (b * CCH + g * CPG) * NTOK;

    float s = 0.f, ss = 0.f;
    for (int i = tid; i < GN_ELEMS; i += 256) {
        float v = xp[i];
        s += v;
        ss += v * v;
    }
    __shared__ float shs[256];
    __shared__ float shq[256];
    shs[tid] = s; shq[tid] = ss;
    __syncthreads();
    for (int o = 128; o > 0; o >>= 1) {
        if (tid < o) { shs[tid] += shs[tid + o]; shq[tid] += shq[tid + o]; }
        __syncthreads();
    }
    const float mean = shs[0] * (1.0f / (float)GN_ELEMS);
    const float var  = shq[0] * (1.0f / (float)GN_ELEMS) - mean * mean;
    const float rstd = rsqrtf(var + 1e-5f);

    float* op = g_xn + (b * CCH + g * CPG) * NTOK;
    for (int i = tid; i < GN_ELEMS; i += 256) {
        int c = g * CPG + (i >> 10);
        op[i] = (xp[i] - mean) * rstd * gw[c] + gb[c];
    }
}

// ===========================================================================
// Kernel 2: QKV GEMM.  Per batch:  W[1536,512] @ xn[512,1024].
// 128x128 tile, BK=8, 256 threads, 8x8 per thread.
// Output routed into g_q/g_k/g_v with layout [b, h, n, d].
// grid = (12, 8, 8)
// ===========================================================================
__global__ void __launch_bounds__(256) qkv_gemm_kernel(const float* __restrict__ W)
{
    const int b  = blockIdx.z;
    const float* X = g_xn + b * CCH * NTOK;
    const int bm = blockIdx.x * 128;   // output channel tile
    const int bn = blockIdx.y * 128;   // token tile

    __shared__ float As[8][128];
    __shared__ float Bs[8][128];

    const int tid = threadIdx.x;
    const int tr  = tid >> 4;          // 0..15
    const int tc  = tid & 15;          // 0..15

    float acc[8][8];
#pragma unroll
    for (int i = 0; i < 8; i++)
#pragma unroll
        for (int j = 0; j < 8; j++) acc[i][j] = 0.f;

    const int arow = tid >> 1;         // 0..127
    const int acol = (tid & 1) * 4;    // 0 or 4
    const int brow = tid >> 5;         // 0..7
    const int bcol = (tid & 31) * 4;   // 0..124

    for (int k0 = 0; k0 < 512; k0 += 8) {
        float4 a4 = *(const float4*)(W + (bm + arow) * 512 + k0 + acol);
        As[acol + 0][arow] = a4.x;
        As[acol + 1][arow] = a4.y;
        As[acol + 2][arow] = a4.z;
        As[acol + 3][arow] = a4.w;
        float4 b4 = *(const float4*)(X + (k0 + brow) * NTOK + bn + bcol);
        *(float4*)&Bs[brow][bcol] = b4;
        __syncthreads();
#pragma unroll
        for (int kk = 0; kk < 8; kk++) {
            float ra[8], rb[8];
            *(float4*)(ra)     = *(const float4*)&As[kk][tr * 8];
            *(float4*)(ra + 4) = *(const float4*)&As[kk][tr * 8 + 4];
            *(float4*)(rb)     = *(const float4*)&Bs[kk][tc * 8];
            *(float4*)(rb + 4) = *(const float4*)&Bs[kk][tc * 8 + 4];
#pragma unroll
            for (int i = 0; i < 8; i++)
#pragma unroll
                for (int j = 0; j < 8; j++)
                    acc[i][j] += ra[i] * rb[j];
        }
        __syncthreads();
    }

    // route: o in [0,1536): which = o/512, head = (o%512)/64, d = o%64
    const int which = bm >> 9;
    float* dst = (which == 0) ? g_q : ((which == 1) ? g_k : g_v);
    const int rem_base = bm & 511;
#pragma unroll
    for (int i = 0; i < 8; i++) {
        int o  = rem_base + tr * 8 + i;
        int h  = o >> 6;
        int dd = o & 63;
        float* row = dst + ((b * NHEADS + h) * NTOK) * DHEAD + dd;
#pragma unroll
        for (int j = 0; j < 8; j++) {
            int n = bn + tc * 8 + j;
            row[n * DHEAD] = acc[i][j];
        }
    }
}

// ===========================================================================
// Kernel 3: attention (flash-style, fp32).
// grid = (16 i-tiles, 8 heads, 8 batch), 256 threads.
// i-tile = 64 query rows, j-tile = 32 keys.
// Thread (tr,tc): S micro 4x2 (i x j), O micro 4x4 (i x d).
// Output: g_ao[b, h*64+d, n]  (channel-major, ready for proj GEMM)
// ===========================================================================
__global__ void __launch_bounds__(256) attn_kernel()
{
    const int it = blockIdx.x;
    const int h  = blockIdx.y;
    const int b  = blockIdx.z;
    const int base = ((b * NHEADS + h) * NTOK) * DHEAD;
    const float* Q = g_q + base;
    const float* K = g_k + base;
    const float* V = g_v + base;

    __shared__ float Qs[64][65];
    __shared__ float Ks[32][65];
    __shared__ float Vs[32][65];
    __shared__ float Ps[64][33];

    const int tid = threadIdx.x;
    const int tr  = tid >> 4;   // 0..15
    const int tc  = tid & 15;   // 0..15

    // load Q tile (64 x 64)
#pragma unroll
    for (int t = 0; t < 4; t++) {
        int e = tid + t * 256;
        int r = e >> 4, c = (e & 15) << 2;
        float4 q4 = *(const float4*)(Q + (it * 64 + r) * DHEAD + c);
        Qs[r][c + 0] = q4.x; Qs[r][c + 1] = q4.y;
        Qs[r][c + 2] = q4.z; Qs[r][c + 3] = q4.w;
    }

    float m[4], l[4], acc[4][4];
#pragma unroll
    for (int i = 0; i < 4; i++) {
        m[i] = -1e30f; l[i] = 0.f;
#pragma unroll
        for (int j = 0; j < 4; j++) acc[i][j] = 0.f;
    }

    for (int j0 = 0; j0 < NTOK; j0 += 32) {
        __syncthreads();   // protect Ks/Vs/Ps reuse from previous iteration
#pragma unroll
        for (int t = 0; t < 2; t++) {
            int e = tid + t * 256;
            int r = e >> 4, c = (e & 15) << 2;
            float4 k4 = *(const float4*)(K + (j0 + r) * DHEAD + c);
            Ks[r][c + 0] = k4.x; Ks[r][c + 1] = k4.y;
            Ks[r][c + 2] = k4.z; Ks[r][c + 3] = k4.w;
            float4 v4 = *(const float4*)(V + (j0 + r) * DHEAD + c);
            Vs[r][c + 0] = v4.x; Vs[r][c + 1] = v4.y;
            Vs[r][c + 2] = v4.z; Vs[r][c + 3] = v4.w;
        }
        __syncthreads();

        // S = Q @ K^T for this tile: s[4][2]
        float s[4][2] = {{0.f, 0.f}, {0.f, 0.f}, {0.f, 0.f}, {0.f, 0.f}};
#pragma unroll 16
        for (int d0 = 0; d0 < 64; d0++) {
            float qa0 = Qs[tr * 4 + 0][d0];
            float qa1 = Qs[tr * 4 + 1][d0];
            float qa2 = Qs[tr * 4 + 2][d0];
            float qa3 = Qs[tr * 4 + 3][d0];
            float kb0 = Ks[tc * 2 + 0][d0];
            float kb1 = Ks[tc * 2 + 1][d0];
            s[0][0] += qa0 * kb0; s[0][1] += qa0 * kb1;
            s[1][0] += qa1 * kb0; s[1][1] += qa1 * kb1;
            s[2][0] += qa2 * kb0; s[2][1] += qa2 * kb1;
            s[3][0] += qa3 * kb0; s[3][1] += qa3 * kb1;
        }

        // scale + row max (across the 16 tc threads: lanes xor 1,2,4,8)
        float mt[4];
#pragma unroll
        for (int i = 0; i < 4; i++) {
            s[i][0] *= 0.125f;
            s[i][1] *= 0.125f;
            mt[i] = fmaxf(s[i][0], s[i][1]);
        }
#pragma unroll
        for (int off = 8; off > 0; off >>= 1) {
#pragma unroll
            for (int i = 0; i < 4; i++)
                mt[i] = fmaxf(mt[i], __shfl_xor_sync(0xffffffffu, mt[i], off));
        }

        float p[4][2], rs[4], fac[4];
#pragma unroll
        for (int i = 0; i < 4; i++) {
            float mn = fmaxf(m[i], mt[i]);
            fac[i] = __expf(m[i] - mn);
            m[i] = mn;
            p[i][0] = __expf(s[i][0] - mn);
            p[i][1] = __expf(s[i][1] - mn);
            rs[i] = p[i][0] + p[i][1];
        }
#pragma unroll
        for (int off = 8; off > 0; off >>= 1) {
#pragma unroll
            for (int i = 0; i < 4; i++)
                rs[i] += __shfl_xor_sync(0xffffffffu, rs[i], off);
        }
#pragma unroll
        for (int i = 0; i < 4; i++) {
            l[i] = l[i] * fac[i] + rs[i];
#pragma unroll
            for (int j = 0; j < 4; j++) acc[i][j] *= fac[i];
            Ps[tr * 4 + i][tc * 2 + 0] = p[i][0];
            Ps[tr * 4 + i][tc * 2 + 1] = p[i][1];
        }
        __syncthreads();

        // O += P @ V : acc[i][dd], dd = tc*4 + jj
#pragma unroll 8
        for (int j = 0; j < 32; j++) {
            float pv0 = Ps[tr * 4 + 0][j];
            float pv1 = Ps[tr * 4 + 1][j];
            float pv2 = Ps[tr * 4 + 2][j];
            float pv3 = Ps[tr * 4 + 3][j];
            float vv0 = Vs[j][tc * 4 + 0];
            float vv1 = Vs[j][tc * 4 + 1];
            float vv2 = Vs[j][tc * 4 + 2];
            float vv3 = Vs[j][tc * 4 + 3];
            acc[0][0] += pv0 * vv0; acc[0][1] += pv0 * vv1; acc[0][2] += pv0 * vv2; acc[0][3] += pv0 * vv3;
            acc[1][0] += pv1 * vv0; acc[1][1] += pv1 * vv1; acc[1][2] += pv1 * vv2; acc[1][3] += pv1 * vv3;
            acc[2][0] += pv2 * vv0; acc[2][1] += pv2 * vv1; acc[2][2] += pv2 * vv2; acc[2][3] += pv2 * vv3;
            acc[3][0] += pv3 * vv0; acc[3][1] += pv3 * vv1; acc[3][2] += pv3 * vv2; acc[3][3] += pv3 * vv3;
        }
    }

    // epilogue: normalize, write channel-major [b, h*64+dd, n]
    float* O = g_ao + (b * CCH + h * DHEAD) * NTOK;
#pragma unroll
    for (int i = 0; i < 4; i++) {
        float inv = 1.0f / l[i];
        int n = it * 64 + tr * 4 + i;
#pragma unroll
        for (int jj = 0; jj < 4; jj++)
            O[(tc * 4 + jj) * NTOK + n] = acc[i][jj] * inv;
    }
}

// ===========================================================================
// Kernel 4: proj GEMM + residual.  Per batch: W[512,512] @ ao[512,1024] + x.
// grid = (4, 8, 8)
// ===========================================================================
__global__ void __launch_bounds__(256) proj_gemm_kernel(
    const float* __restrict__ W,
    const float* __restrict__ x,
    float* __restrict__ out)
{
    const int b  = blockIdx.z;
    const float* Bm = g_ao + b * CCH * NTOK;
    const int bm = blockIdx.x * 128;
    const int bn = blockIdx.y * 128;

    __shared__ float As[8][128];
    __shared__ float Bs[8][128];

    const int tid = threadIdx.x;
    const int tr  = tid >> 4;
    const int tc  = tid & 15;

    float acc[8][8];
#pragma unroll
    for (int i = 0; i < 8; i++)
#pragma unroll
        for (int j = 0; j < 8; j++) acc[i][j] = 0.f;

    const int arow = tid >> 1;
    const int acol = (tid & 1) * 4;
    const int brow = tid >> 5;
    const int bcol = (tid & 31) * 4;

    for (int k0 = 0; k0 < 512; k0 += 8) {
        float4 a4 = *(const float4*)(W + (bm + arow) * 512 + k0 + acol);
        As[acol + 0][arow] = a4.x;
        As[acol + 1][arow] = a4.y;
        As[acol + 2][arow] = a4.z;
        As[acol + 3][arow] = a4.w;
        float4 b4 = *(const float4*)(Bm + (k0 + brow) * NTOK + bn + bcol);
        *(float4*)&Bs[brow][bcol] = b4;
        __syncthreads();
#pragma unroll
        for (int kk = 0; kk < 8; kk++) {
            float ra[8], rb[8];
            *(float4*)(ra)     = *(const float4*)&As[kk][tr * 8];
            *(float4*)(ra + 4) = *(const float4*)&As[kk][tr * 8 + 4];
            *(float4*)(rb)     = *(const float4*)&Bs[kk][tc * 8];
            *(float4*)(rb + 4) = *(const float4*)&Bs[kk][tc * 8 + 4];
#pragma unroll
            for (int i = 0; i < 8; i++)
#pragma unroll
                for (int j = 0; j < 8; j++)
                    acc[i][j] += ra[i] * rb[j];
        }
        __syncthreads();
    }

#pragma unroll
    for (int i = 0; i < 8; i++) {
        int o = bm + tr * 8 + i;
        const float* xr = x   + (b * CCH + o) * NTOK + bn + tc * 8;
        float*       orw = out + (b * CCH + o) * NTOK + bn + tc * 8;
#pragma unroll
        for (int j = 0; j < 8; j++)
            orw[j] = xr[j] + acc[i][j];
    }
}

// ===========================================================================
// launch
// ===========================================================================
extern "C" void kernel_launch(void* const* d_in, const int* in_sizes, int n_in,
                              void* d_out, int out_size)
{
    const float* x     = (const float*)d_in[0];
    const float* gn_w  = (const float*)d_in[1];
    const float* gn_b  = (const float*)d_in[2];
    const float* w_qkv = (const float*)d_in[3];
    const float* w_prj = (const float*)d_in[4];
    float* out = (float*)d_out;

    groupnorm_kernel<<<BATCH * NGROUP, 256>>>(x, gn_w, gn_b);

    dim3 gq(12, 8, BATCH);   // 1536/128, 1024/128, B
    qkv_gemm_kernel<<<gq, 256>>>(w_qkv);

    dim3 ga(16, NHEADS, BATCH);  // 1024/64 i-tiles
    attn_kernel<<<ga, 256>>>();

    dim3 gp(4, 8, BATCH);    // 512/128, 1024/128, B
    proj_gemm_kernel<<<gp, 256>>>(w_prj, x, out);
}

// round 2
// speedup vs baseline: 2.4435x; 2.4435x over previous
#include <cuda_runtime.h>
#include <math.h>
#include <stdint.h>

#define BATCH   8
#define CCH     512
#define NHEADS  8
#define DHEAD   64
#define NTOK    1024
#define NGROUP  32
#define CPG     16
#define GN_ELEMS (CPG * NTOK)

// ---------------- scratch (alloc-free: __device__ globals) ----------------
// All hold tf32 bit patterns (stored as float bits) unless noted.
__device__ float g_xn[BATCH * CCH * NTOK];            // GN out (tf32 bits) [b, c, n]
__device__ float g_q [BATCH * NHEADS * NTOK * DHEAD]; // tf32 bits, q pre-scaled by 1/8
__device__ float g_k [BATCH * NHEADS * NTOK * DHEAD]; // tf32 bits
__device__ float g_v [BATCH * NHEADS * NTOK * DHEAD]; // tf32 bits
__device__ float g_ao[BATCH * CCH * NTOK];            // attn out (tf32 bits) [b, c, n]

// ---------------- helpers ----------------
__device__ __forceinline__ uint32_t f2tf(float f) {
    uint32_t u;
    asm("cvt.rna.tf32.f32 %0, %1;" : "=r"(u) : "f"(f));
    return u;
}

__device__ __forceinline__ void mma_tf32(float c[4],
    uint32_t a0, uint32_t a1, uint32_t a2, uint32_t a3,
    uint32_t b0, uint32_t b1)
{
    asm volatile(
        "mma.sync.aligned.m16n8k8.row.col.f32.tf32.tf32.f32 "
        "{%0,%1,%2,%3}, {%4,%5,%6,%7}, {%8,%9}, {%0,%1,%2,%3};"
        : "+f"(c[0]), "+f"(c[1]), "+f"(c[2]), "+f"(c[3])
        : "r"(a0), "r"(a1), "r"(a2), "r"(a3), "r"(b0), "r"(b1));
}

// ===========================================================================
// Kernel 1: GroupNorm -> tf32 bits. grid = 256 blocks (b*32+g), 256 threads.
// ===========================================================================
__global__ void __launch_bounds__(256) groupnorm_kernel(
    const float* __restrict__ x,
    const float* __restrict__ gw,
    const float* __restrict__ gb)
{
    const int b = blockIdx.x >> 5;
    const int g = blockIdx.x & 31;
    const int tid = threadIdx.x;
    const float* xp = x + (b * CCH + g * CPG) * NTOK;

    float s = 0.f, ss = 0.f;
    for (int i = tid; i < GN_ELEMS; i += 256) {
        float v = xp[i];
        s += v; ss += v * v;
    }
    __shared__ float shs[256];
    __shared__ float shq[256];
    shs[tid] = s; shq[tid] = ss;
    __syncthreads();
    for (int o = 128; o > 0; o >>= 1) {
        if (tid < o) { shs[tid] += shs[tid + o]; shq[tid] += shq[tid + o]; }
        __syncthreads();
    }
    const float mean = shs[0] * (1.0f / (float)GN_ELEMS);
    const float var  = shq[0] * (1.0f / (float)GN_ELEMS) - mean * mean;
    const float rstd = rsqrtf(var + 1e-5f);

    float* op = g_xn + (b * CCH + g * CPG) * NTOK;
    for (int i = tid; i < GN_ELEMS; i += 256) {
        int c = g * CPG + (i >> 10);
        float v = (xp[i] - mean) * rstd * gw[c] + gb[c];
        op[i] = __uint_as_float(f2tf(v));
    }
}

// ===========================================================================
// tf32 MMA GEMM template: D[M,N] = W[M,512] @ B[512,1024] per batch.
// Block tile 128x128, BK=32, 8 warps (2x4), warp tile 64x32.
// W is raw fp32 (cvt at smem store); B source already tf32 bits.
// ===========================================================================
#define BK 32
#define SPAD 136   // 136 mod 32 == 8 -> conflict-free fragment loads

struct GemmCtx {
    float acc[4][4][4];
    int g, tig, wm, wn;
};

__device__ __forceinline__ void gemm_main(
    const float* __restrict__ W, int Wld,
    const uint32_t* __restrict__ Bsrc,   // [512,1024] tf32 bits
    int bm, int bn, GemmCtx& ctx)
{
    __shared__ uint32_t As[BK][SPAD];
    __shared__ uint32_t Bs[BK][SPAD];

    const int tid = threadIdx.x;
    const int lane = tid & 31;
    const int warpid = tid >> 5;
    ctx.g = lane >> 2;
    ctx.tig = lane & 3;
    ctx.wm = (warpid >> 2) * 64;
    ctx.wn = (warpid & 3) * 32;

#pragma unroll
    for (int mt = 0; mt < 4; mt++)
#pragma unroll
        for (int nt = 0; nt < 4; nt++)
#pragma unroll
            for (int r = 0; r < 4; r++) ctx.acc[mt][nt][r] = 0.f;

    const int am = tid >> 1;            // 0..127
    const int akb = (tid & 1) * 16;     // 0 or 16
    const int bk = tid >> 3;            // 0..31
    const int bnb = (tid & 7) * 16;     // 0..112

    for (int k0 = 0; k0 < 512; k0 += BK) {
        // W tile -> As[k][m] transposed with tf32 cvt
#pragma unroll
        for (int j = 0; j < 4; j++) {
            float4 w4 = *(const float4*)(W + (size_t)(bm + am) * Wld + k0 + akb + j * 4);
            As[akb + j * 4 + 0][am] = f2tf(w4.x);
            As[akb + j * 4 + 1][am] = f2tf(w4.y);
            As[akb + j * 4 + 2][am] = f2tf(w4.z);
            As[akb + j * 4 + 3][am] = f2tf(w4.w);
        }
        // B tile -> Bs[k][n] direct copy (already tf32 bits)
#pragma unroll
        for (int j = 0; j < 4; j++) {
            uint4 b4 = *(const uint4*)(Bsrc + (size_t)(k0 + bk) * NTOK + bn + bnb + j * 4);
            *(uint4*)&Bs[bk][bnb + j * 4] = b4;
        }
        __syncthreads();

#pragma unroll
        for (int ks = 0; ks < BK / 8; ks++) {
            const int kk = ks * 8;
            uint32_t a[4][4], bb[4][2];
#pragma unroll
            for (int mt = 0; mt < 4; mt++) {
                int mrow = ctx.wm + mt * 16 + ctx.g;
                a[mt][0] = As[kk + ctx.tig][mrow];
                a[mt][1] = As[kk + ctx.tig][mrow + 8];
                a[mt][2] = As[kk + ctx.tig + 4][mrow];
                a[mt][3] = As[kk + ctx.tig + 4][mrow + 8];
            }
#pragma unroll
            for (int nt = 0; nt < 4; nt++) {
                int ncol = ctx.wn + nt * 8 + ctx.g;
                bb[nt][0] = Bs[kk + ctx.tig][ncol];
                bb[nt][1] = Bs[kk + ctx.tig + 4][ncol];
            }
#pragma unroll
            for (int mt = 0; mt < 4; mt++)
#pragma unroll
                for (int nt = 0; nt < 4; nt++)
                    mma_tf32(ctx.acc[mt][nt], a[mt][0], a[mt][1], a[mt][2], a[mt][3],
                             bb[nt][0], bb[nt][1]);
        }
        __syncthreads();
    }
}

// ---- QKV GEMM: W[1536,512] @ xn -> g_q/g_k/g_v [b,h,n,d] tf32 bits ----
__global__ void __launch_bounds__(256) qkv_gemm_kernel(const float* __restrict__ W)
{
    const int b  = blockIdx.z;
    const int bm = blockIdx.x * 128;
    const int bn = blockIdx.y * 128;
    const uint32_t* X = (const uint32_t*)(g_xn + (size_t)b * CCH * NTOK);

    GemmCtx ctx;
    gemm_main(W, 512, X, bm, bn, ctx);

    const int which = bm >> 9;   // 0=q 1=k 2=v (uniform per block)
    float* dst = (which == 0) ? g_q : ((which == 1) ? g_k : g_v);
    const float qs = (which == 0) ? 0.125f : 1.0f;

#pragma unroll
    for (int mt = 0; mt < 4; mt++) {
#pragma unroll
        for (int rr = 0; rr < 2; rr++) {
            int o   = (bm & 511) + ctx.wm + mt * 16 + ctx.g + rr * 8;
            int h   = o >> 6;
            int dd  = o & 63;
            float* row = dst + (((size_t)b * NHEADS + h) * NTOK) * DHEAD + dd;
#pragma unroll
            for (int nt = 0; nt < 4; nt++) {
                int n = bn + ctx.wn + nt * 8 + ctx.tig * 2;
                float v0 = ctx.acc[mt][nt][rr * 2 + 0] * qs;
                float v1 = ctx.acc[mt][nt][rr * 2 + 1] * qs;
                row[(size_t)n * DHEAD]       = __uint_as_float(f2tf(v0));
                row[(size_t)(n + 1) * DHEAD] = __uint_as_float(f2tf(v1));
            }
        }
    }
}

// ---- proj GEMM: W[512,512] @ ao + x -> out (fp32) ----
__global__ void __launch_bounds__(256) proj_gemm_kernel(
    const float* __restrict__ W,
    const float* __restrict__ x,
    float* __restrict__ out)
{
    const int b  = blockIdx.z;
    const int bm = blockIdx.x * 128;
    const int bn = blockIdx.y * 128;
    const uint32_t* AO = (const uint32_t*)(g_ao + (size_t)b * CCH * NTOK);

    GemmCtx ctx;
    gemm_main(W, 512, AO, bm, bn, ctx);

#pragma unroll
    for (int mt = 0; mt < 4; mt++) {
#pragma unroll
        for (int rr = 0; rr < 2; rr++) {
            int o = bm + ctx.wm + mt * 16 + ctx.g + rr * 8;
            const float* xr  = x   + ((size_t)b * CCH + o) * NTOK;
            float*       orw = out + ((size_t)b * CCH + o) * NTOK;
#pragma unroll
            for (int nt = 0; nt < 4; nt++) {
                int n = bn + ctx.wn + nt * 8 + ctx.tig * 2;
                orw[n]     = xr[n]     + ctx.acc[mt][nt][rr * 2 + 0];
                orw[n + 1] = xr[n + 1] + ctx.acc[mt][nt][rr * 2 + 1];
            }
        }
    }
}

// ===========================================================================
// Kernel 3: flash attention, tf32 MMA.
// grid = (16 i-tiles, 8 heads, 8 batch), 128 threads (4 warps).
// Warp w owns 16 query rows. j-tile = 32 keys.
// ===========================================================================
__global__ void __launch_bounds__(128) attn_kernel()
{
    const int it = blockIdx.x;
    const int h  = blockIdx.y;
    const int b  = blockIdx.z;
    const size_t base = (((size_t)b * NHEADS + h) * NTOK) * DHEAD;
    const uint32_t* Q = (const uint32_t*)g_q + base;
    const uint32_t* K = (const uint32_t*)g_k + base;
    const uint32_t* V = (const uint32_t*)g_v + base;

    __shared__ uint32_t Ks[32][68];     // 68 mod 32 = 4: b0=Ks[j][d] conflict-free
    __shared__ uint32_t Vs[32][72];     // 72 mod 32 = 8: b0=Vs[k][d] conflict-free
    __shared__ uint32_t Ps[4][16][36];  // 36 mod 32 = 4: a0=Ps[g][k] conflict-free

    const int tid  = threadIdx.x;
    const int lane = tid & 31;
    const int w    = tid >> 5;
    const int g    = lane >> 2;
    const int tig  = lane & 3;

    // preload Q fragments for this warp's 16 rows (q already scaled by 1/8)
    const uint32_t* Qw = Q + (size_t)(it * 64 + w * 16) * DHEAD;
    uint32_t qa[8][4];
#pragma unroll
    for (int ks = 0; ks < 8; ks++) {
        int c = ks * 8 + tig;
        qa[ks][0] = Qw[(size_t)g * 64 + c];
        qa[ks][1] = Qw[(size_t)(g + 8) * 64 + c];
        qa[ks][2] = Qw[(size_t)g * 64 + c + 4];
        qa[ks][3] = Qw[(size_t)(g + 8) * 64 + c + 4];
    }

    float m0 = -1e30f, m1 = -1e30f, l0 = 0.f, l1 = 0.f;
    float o[8][4];
#pragma unroll
    for (int nt = 0; nt < 8; nt++)
#pragma unroll
        for (int r = 0; r < 4; r++) o[nt][r] = 0.f;

    const int lr = tid >> 2;          // 0..31 load row
    const int lc = (tid & 3) * 16;    // 0,16,32,48

    for (int j0 = 0; j0 < NTOK; j0 += 32) {
        __syncthreads();
#pragma unroll
        for (int j = 0; j < 4; j++) {
            uint4 k4 = *(const uint4*)(K + (size_t)(j0 + lr) * 64 + lc + j * 4);
            *(uint4*)&Ks[lr][lc + j * 4] = k4;
            uint4 v4 = *(const uint4*)(V + (size_t)(j0 + lr) * 64 + lc + j * 4);
            *(uint4*)&Vs[lr][lc + j * 4] = v4;
        }
        __syncthreads();

        // S = Q @ K^T : 4 n-tiles (32 keys), k = 64 over 8 steps
        float s[4][4];
#pragma unroll
        for (int nt = 0; nt < 4; nt++)
#pragma unroll
            for (int r = 0; r < 4; r++) s[nt][r] = 0.f;
#pragma unroll
        for (int ks = 0; ks < 8; ks++) {
            const int kk = ks * 8;
#pragma unroll
            for (int nt = 0; nt < 4; nt++) {
                uint32_t b0 = Ks[nt * 8 + g][kk + tig];
                uint32_t b1 = Ks[nt * 8 + g][kk + tig + 4];
                mma_tf32(s[nt], qa[ks][0], qa[ks][1], qa[ks][2], qa[ks][3], b0, b1);
            }
        }

        // online softmax (rows g and g+8)
        float mt0 = -1e30f, mt1 = -1e30f;
#pragma unroll
        for (int nt = 0; nt < 4; nt++) {
            mt0 = fmaxf(mt0, fmaxf(s[nt][0], s[nt][1]));
            mt1 = fmaxf(mt1, fmaxf(s[nt][2], s[nt][3]));
        }
        mt0 = fmaxf(mt0, __shfl_xor_sync(0xffffffffu, mt0, 1));
        mt0 = fmaxf(mt0, __shfl_xor_sync(0xffffffffu, mt0, 2));
        mt1 = fmaxf(mt1, __shfl_xor_sync(0xffffffffu, mt1, 1));
        mt1 = fmaxf(mt1, __shfl_xor_sync(0xffffffffu, mt1, 2));

        float mn0 = fmaxf(m0, mt0), mn1 = fmaxf(m1, mt1);
        float fac0 = __expf(m0 - mn0), fac1 = __expf(m1 - mn1);
        m0 = mn0; m1 = mn1;

        float rs0 = 0.f, rs1 = 0.f;
#pragma unroll
        for (int nt = 0; nt < 4; nt++) {
            float p0 = __expf(s[nt][0] - mn0);
            float p1 = __expf(s[nt][1] - mn0);
            float p2 = __expf(s[nt][2] - mn1);
            float p3 = __expf(s[nt][3] - mn1);
            rs0 += p0 + p1; rs1 += p2 + p3;
            int c = nt * 8 + tig * 2;
            Ps[w][g][c]         = f2tf(p0);
            Ps[w][g][c + 1]     = f2tf(p1);
            Ps[w][g + 8][c]     = f2tf(p2);
            Ps[w][g + 8][c + 1] = f2tf(p3);
        }
        rs0 += __shfl_xor_sync(0xffffffffu, rs0, 1);
        rs0 += __shfl_xor_sync(0xffffffffu, rs0, 2);
        rs1 += __shfl_xor_sync(0xffffffffu, rs1, 1);
        rs1 += __shfl_xor_sync(0xffffffffu, rs1, 2);
        l0 = l0 * fac0 + rs0;
        l1 = l1 * fac1 + rs1;
#pragma unroll
        for (int nt = 0; nt < 8; nt++) {
            o[nt][0] *= fac0; o[nt][1] *= fac0;
            o[nt][2] *= fac1; o[nt][3] *= fac1;
        }
        __syncwarp();

        // O += P @ V : 8 n-tiles (d=64), k = 32 over 4 steps
#pragma unroll
        for (int ks = 0; ks < 4; ks++) {
            const int kk = ks * 8;
            uint32_t pa0 = Ps[w][g][kk + tig];
            uint32_t pa1 = Ps[w][g + 8][kk + tig];
            uint32_t pa2 = Ps[w][g][kk + tig + 4];
            uint32_t pa3 = Ps[w][g + 8][kk + tig + 4];
#pragma unroll
            for (int nt = 0; nt < 8; nt++) {
                uint32_t b0 = Vs[kk + tig][nt * 8 + g];
                uint32_t b1 = Vs[kk + tig + 4][nt * 8 + g];
                mma_tf32(o[nt], pa0, pa1, pa2, pa3, b0, b1);
            }
        }
        __syncwarp();   // Ps reuse next iteration
    }

    // epilogue: normalize, cvt to tf32 bits, write channel-major [b, h*64+d, n]
    const float inv0 = 1.0f / l0, inv1 = 1.0f / l1;
    uint32_t* O = (uint32_t*)g_ao + ((size_t)b * CCH + h * DHEAD) * NTOK;
    const int n0 = it * 64 + w * 16 + g;
#pragma unroll
    for (int nt = 0; nt < 8; nt++) {
        int d = nt * 8 + tig * 2;
        O[(size_t)d * NTOK + n0]           = f2tf(o[nt][0] * inv0);
        O[(size_t)(d + 1) * NTOK + n0]     = f2tf(o[nt][1] * inv0);
        O[(size_t)d * NTOK + n0 + 8]       = f2tf(o[nt][2] * inv1);
        O[(size_t)(d + 1) * NTOK + n0 + 8] = f2tf(o[nt][3] * inv1);
    }
}

// ===========================================================================
// launch
// ===========================================================================
extern "C" void kernel_launch(void* const* d_in, const int* in_sizes, int n_in,
                              void* d_out, int out_size)
{
    const float* x     = (const float*)d_in[0];
    const float* gn_w  = (const float*)d_in[1];
    const float* gn_b  = (const float*)d_in[2];
    const float* w_qkv = (const float*)d_in[3];
    const float* w_prj = (const float*)d_in[4];
    float* out = (float*)d_out;

    groupnorm_kernel<<<BATCH * NGROUP, 256>>>(x, gn_w, gn_b);

    dim3 gq(12, 8, BATCH);
    qkv_gemm_kernel<<<gq, 256>>>(w_qkv);

    dim3 ga(16, NHEADS, BATCH);
    attn_kernel<<<ga, 128>>>();

    dim3 gp(4, 8, BATCH);
    proj_gemm_kernel<<<gp, 256>>>(w_prj, x, out);
}

// round 3
// speedup vs baseline: 6.2727x; 2.5671x over previous
#include <cuda_runtime.h>
#include <cuda_bf16.h>
#include <math.h>
#include <stdint.h>

#define BATCH   8
#define CCH     512
#define NHEADS  8
#define DHEAD   64
#define NTOK    1024
#define NGROUP  32
#define CPG     16
#define GN_ELEMS (CPG * NTOK)

// ---------------- scratch (alloc-free: __device__ globals) ----------------
__device__ __nv_bfloat16 g_xn[BATCH * CCH * NTOK];            // GN out [b, c, n]
__device__ __nv_bfloat16 g_q [BATCH * NHEADS * NTOK * DHEAD]; // [b,h,n,d], q pre-scaled 1/8
__device__ __nv_bfloat16 g_k [BATCH * NHEADS * NTOK * DHEAD];
__device__ __nv_bfloat16 g_v [BATCH * NHEADS * NTOK * DHEAD];
__device__ __nv_bfloat16 g_ao[BATCH * CCH * NTOK];            // attn out [b, c, n]
__device__ __nv_bfloat16 g_wqkv[1536 * 512];                  // bf16 weights
__device__ __nv_bfloat16 g_wproj[512 * 512];

// ---------------- helpers ----------------
__device__ __forceinline__ uint32_t sptr(const void* p) {
    return (uint32_t)__cvta_generic_to_shared(p);
}
__device__ __forceinline__ void ldsm4(uint32_t r[4], uint32_t addr) {
    asm volatile("ldmatrix.sync.aligned.m8n8.x4.shared.b16 {%0,%1,%2,%3}, [%4];"
                 : "=r"(r[0]), "=r"(r[1]), "=r"(r[2]), "=r"(r[3]) : "r"(addr));
}
__device__ __forceinline__ void ldsm4t(uint32_t r[4], uint32_t addr) {
    asm volatile("ldmatrix.sync.aligned.m8n8.x4.trans.shared.b16 {%0,%1,%2,%3}, [%4];"
                 : "=r"(r[0]), "=r"(r[1]), "=r"(r[2]), "=r"(r[3]) : "r"(addr));
}
__device__ __forceinline__ void mma_bf16(float c[4], const uint32_t a[4],
                                         uint32_t b0, uint32_t b1) {
    asm volatile(
        "mma.sync.aligned.m16n8k16.row.col.f32.bf16.bf16.f32 "
        "{%0,%1,%2,%3},{%4,%5,%6,%7},{%8,%9},{%0,%1,%2,%3};"
        : "+f"(c[0]), "+f"(c[1]), "+f"(c[2]), "+f"(c[3])
        : "r"(a[0]), "r"(a[1]), "r"(a[2]), "r"(a[3]), "r"(b0), "r"(b1));
}
__device__ __forceinline__ uint32_t packbf(float lo, float hi) {
    uint32_t d;
    asm("cvt.rn.bf16x2.f32 %0, %1, %2;" : "=r"(d) : "f"(hi), "f"(lo));
    return d;
}
__device__ __forceinline__ void cp16(uint32_t smem, const void* g) {
    asm volatile("cp.async.ca.shared.global [%0], [%1], 16;" :: "r"(smem), "l"(g));
}
__device__ __forceinline__ void cp_commit() { asm volatile("cp.async.commit_group;"); }
__device__ __forceinline__ void cp_wait1()  { asm volatile("cp.async.wait_group 1;"); }
__device__ __forceinline__ void cp_wait0()  { asm volatile("cp.async.wait_group 0;"); }

// ===========================================================================
// Kernel 0: convert fp32 weights -> bf16
// ===========================================================================
__global__ void __launch_bounds__(256) convert_w_kernel(
    const float* __restrict__ src, __nv_bfloat16* __restrict__ dst, int n4)
{
    int i = blockIdx.x * 256 + threadIdx.x;
    if (i >= n4) return;
    float4 v = *(const float4*)(src + (size_t)i * 4);
    uint32_t lo = packbf(v.x, v.y);
    uint32_t hi = packbf(v.z, v.w);
    *(uint2*)(dst + (size_t)i * 4) = make_uint2(lo, hi);
}

// ===========================================================================
// Kernel 1: GroupNorm -> bf16. grid = 256 blocks (b*32+g), 256 threads.
// ===========================================================================
__global__ void __launch_bounds__(256) groupnorm_kernel(
    const float* __restrict__ x,
    const float* __restrict__ gw,
    const float* __restrict__ gb)
{
    const int b = blockIdx.x >> 5;
    const int g = blockIdx.x & 31;
    const int tid = threadIdx.x;
    const float* xp = x + ((size_t)b * CCH + g * CPG) * NTOK;

    float s = 0.f, ss = 0.f;
    for (int i = tid * 2; i < GN_ELEMS; i += 512) {
        float2 v = *(const float2*)(xp + i);
        s += v.x + v.y;
        ss += v.x * v.x + v.y * v.y;
    }
    __shared__ float shs[256];
    __shared__ float shq[256];
    shs[tid] = s; shq[tid] = ss;
    __syncthreads();
    for (int o = 128; o > 0; o >>= 1) {
        if (tid < o) { shs[tid] += shs[tid + o]; shq[tid] += shq[tid + o]; }
        __syncthreads();
    }
    const float mean = shs[0] * (1.0f / (float)GN_ELEMS);
    const float var  = shq[0] * (1.0f / (float)GN_ELEMS) - mean * mean;
    const float rstd = rsqrtf(var + 1e-5f);

    uint32_t* op = (uint32_t*)(g_xn + ((size_t)b * CCH + g * CPG) * NTOK);
    for (int i = tid * 2; i < GN_ELEMS; i += 512) {
        int c = g * CPG + (i >> 10);
        float2 v = *(const float2*)(xp + i);
        float a0 = (v.x - mean) * rstd * gw[c] + gb[c];
        float a1 = (v.y - mean) * rstd * gw[c] + gb[c];
        op[i >> 1] = packbf(a0, a1);
    }
}

// ===========================================================================
// bf16 GEMM core: D[128,128] tile of W[M,512] @ B[512,1024].
// 8 warps (2x4), warp tile 64x32, BK=32, cp.async 2-stage.
// A smem [128][40] pad (20-word stride perm), B smem [32][136] pad (r*4 mod 32).
// ===========================================================================
#define APAD 40
#define BPAD 136

struct GemmCtx { float acc[4][4][4]; int g, t, wm, wn; };

__device__ __forceinline__ void gemm_main_bf16(
    const __nv_bfloat16* __restrict__ Wbf,     // [M,512]
    const __nv_bfloat16* __restrict__ Xbf,     // [512,1024]
    int bm, int bn, GemmCtx& ctx)
{
    __shared__ __align__(16) __nv_bfloat16 As[2][128][APAD];
    __shared__ __align__(16) __nv_bfloat16 Bs[2][32][BPAD];

    const int tid = threadIdx.x;
    const int lane = tid & 31;
    const int warpid = tid >> 5;
    ctx.g = lane >> 2;
    ctx.t = lane & 3;
    ctx.wm = (warpid >> 2) * 64;
    ctx.wn = (warpid & 3) * 32;

#pragma unroll
    for (int mt = 0; mt < 4; mt++)
#pragma unroll
        for (int nt = 0; nt < 4; nt++)
#pragma unroll
            for (int r = 0; r < 4; r++) ctx.acc[mt][nt][r] = 0.f;

    const int ar = tid >> 1, aq = (tid & 1) * 16;
    const int br = tid >> 3, bq = (tid & 7) * 16;

    // prologue: stage chunks 0,1
#pragma unroll
    for (int kc = 0; kc < 2; kc++) {
        const int k0 = kc * 32;
        cp16(sptr(&As[kc][ar][aq]),     Wbf + (size_t)(bm + ar) * 512 + k0 + aq);
        cp16(sptr(&As[kc][ar][aq + 8]), Wbf + (size_t)(bm + ar) * 512 + k0 + aq + 8);
        cp16(sptr(&Bs[kc][br][bq]),     Xbf + (size_t)(k0 + br) * NTOK + bn + bq);
        cp16(sptr(&Bs[kc][br][bq + 8]), Xbf + (size_t)(k0 + br) * NTOK + bn + bq + 8);
        cp_commit();
    }

    for (int kc = 0; kc < 16; kc++) {
        const int s = kc & 1;
        if (kc < 15) cp_wait1(); else cp_wait0();
        __syncthreads();

        // lane addressing constants
        const int l7 = lane & 7, l8 = (lane >> 3) & 1, l16 = lane >> 4;
#pragma unroll
        for (int kk = 0; kk < 32; kk += 16) {
            uint32_t a[4][4], bb[4][2];
#pragma unroll
            for (int mt = 0; mt < 4; mt++) {
                int row = ctx.wm + mt * 16 + l7 + l8 * 8;
                int col = kk + l16 * 8;
                ldsm4(a[mt], sptr(&As[s][row][col]));
            }
#pragma unroll
            for (int np = 0; np < 2; np++) {
                int row = kk + l7 + l8 * 8;
                int col = ctx.wn + np * 16 + l16 * 8;
                uint32_t r[4];
                ldsm4t(r, sptr(&Bs[s][row][col]));
                bb[np * 2][0] = r[0]; bb[np * 2][1] = r[1];
                bb[np * 2 + 1][0] = r[2]; bb[np * 2 + 1][1] = r[3];
            }
#pragma unroll
            for (int mt = 0; mt < 4; mt++)
#pragma unroll
                for (int nt = 0; nt < 4; nt++)
                    mma_bf16(ctx.acc[mt][nt], a[mt], bb[nt][0], bb[nt][1]);
        }
        __syncthreads();
        if (kc + 2 < 16) {
            const int k0 = (kc + 2) * 32;
            cp16(sptr(&As[s][ar][aq]),     Wbf + (size_t)(bm + ar) * 512 + k0 + aq);
            cp16(sptr(&As[s][ar][aq + 8]), Wbf + (size_t)(bm + ar) * 512 + k0 + aq + 8);
            cp16(sptr(&Bs[s][br][bq]),     Xbf + (size_t)(k0 + br) * NTOK + bn + bq);
            cp16(sptr(&Bs[s][br][bq + 8]), Xbf + (size_t)(k0 + br) * NTOK + bn + bq + 8);
            cp_commit();
        } else {
            cp_commit();   // keep group count consistent for wait_group
        }
    }
}

// ---- QKV GEMM -> g_q/g_k/g_v [b,h,n,d] bf16 ----
__global__ void __launch_bounds__(256) qkv_gemm_kernel()
{
    const int b  = blockIdx.z;
    const int bm = blockIdx.x * 128;
    const int bn = blockIdx.y * 128;
    const __nv_bfloat16* X = g_xn + (size_t)b * CCH * NTOK;

    GemmCtx ctx;
    gemm_main_bf16(g_wqkv, X, bm, bn, ctx);

    const int which = bm >> 9;
    __nv_bfloat16* dst = (which == 0) ? g_q : ((which == 1) ? g_k : g_v);
    const float qs = (which == 0) ? 0.125f : 1.0f;

#pragma unroll
    for (int mt = 0; mt < 4; mt++) {
#pragma unroll
        for (int rr = 0; rr < 2; rr++) {
            int o  = (bm & 511) + ctx.wm + mt * 16 + ctx.g + rr * 8;
            int h  = o >> 6;
            int dd = o & 63;
            __nv_bfloat16* row = dst + (((size_t)b * NHEADS + h) * NTOK) * DHEAD + dd;
#pragma unroll
            for (int nt = 0; nt < 4; nt++) {
                int n = bn + ctx.wn + nt * 8 + ctx.t * 2;
                row[(size_t)n * DHEAD]       = __float2bfloat16(ctx.acc[mt][nt][rr * 2 + 0] * qs);
                row[(size_t)(n + 1) * DHEAD] = __float2bfloat16(ctx.acc[mt][nt][rr * 2 + 1] * qs);
            }
        }
    }
}

// ---- proj GEMM + residual -> out fp32 ----
__global__ void __launch_bounds__(256) proj_gemm_kernel(
    const float* __restrict__ x, float* __restrict__ out)
{
    const int b  = blockIdx.z;
    const int bm = blockIdx.x * 128;
    const int bn = blockIdx.y * 128;
    const __nv_bfloat16* AO = g_ao + (size_t)b * CCH * NTOK;

    GemmCtx ctx;
    gemm_main_bf16(g_wproj, AO, bm, bn, ctx);

#pragma unroll
    for (int mt = 0; mt < 4; mt++) {
#pragma unroll
        for (int rr = 0; rr < 2; rr++) {
            int o = bm + ctx.wm + mt * 16 + ctx.g + rr * 8;
            const float* xr  = x   + ((size_t)b * CCH + o) * NTOK;
            float*       orw = out + ((size_t)b * CCH + o) * NTOK;
#pragma unroll
            for (int nt = 0; nt < 4; nt++) {
                int n = bn + ctx.wn + nt * 8 + ctx.t * 2;
                orw[n]     = xr[n]     + ctx.acc[mt][nt][rr * 2 + 0];
                orw[n + 1] = xr[n + 1] + ctx.acc[mt][nt][rr * 2 + 1];
            }
        }
    }
}

// ===========================================================================
// Kernel 3: flash attention, bf16 MMA + ldmatrix, cp.async KV pipeline.
// grid = (16, 8, 8), 128 threads (4 warps, 16 q-rows each). j-tile = 32.
// ===========================================================================
#define KVPAD 72

__global__ void __launch_bounds__(128) attn_kernel()
{
    const int it = blockIdx.x;
    const int h  = blockIdx.y;
    const int b  = blockIdx.z;
    const size_t base = (((size_t)b * NHEADS + h) * NTOK) * DHEAD;
    const __nv_bfloat16* Q = g_q + base;
    const __nv_bfloat16* K = g_k + base;
    const __nv_bfloat16* V = g_v + base;

    __shared__ __align__(16) __nv_bfloat16 Qs[64][KVPAD];
    __shared__ __align__(16) __nv_bfloat16 Ks[2][32][KVPAD];
    __shared__ __align__(16) __nv_bfloat16 Vs[2][32][KVPAD];

    const int tid  = threadIdx.x;
    const int lane = tid & 31;
    const int w    = tid >> 5;
    const int g    = lane >> 2;
    const int t    = lane & 3;
    const int l7 = lane & 7, l8 = (lane >> 3) & 1, l16 = lane >> 4;

    // stage Q tile (64x64) into smem
    {
        int row = tid >> 1;
        int cb  = (tid & 1) * 32;
#pragma unroll
        for (int q = 0; q < 4; q++) {
            uint4 v = *(const uint4*)(Q + (size_t)(it * 64 + row) * 64 + cb + q * 8);
            *(uint4*)&Qs[row][cb + q * 8] = v;
        }
    }
    // prologue KV: stage tiles 0,1
    {
        int row = tid >> 2;
        int cb  = (tid & 3) * 16;
#pragma unroll
        for (int jc = 0; jc < 2; jc++) {
            const __nv_bfloat16* Kp = K + (size_t)(jc * 32 + row) * 64 + cb;
            const __nv_bfloat16* Vp = V + (size_t)(jc * 32 + row) * 64 + cb;
            cp16(sptr(&Ks[jc][row][cb]),     Kp);
            cp16(sptr(&Ks[jc][row][cb + 8]), Kp + 8);
            cp16(sptr(&Vs[jc][row][cb]),     Vp);
            cp16(sptr(&Vs[jc][row][cb + 8]), Vp + 8);
            cp_commit();
        }
    }
    __syncthreads();

    // preload Q fragments: qa[ks][4], ks = d/16
    uint32_t qa[4][4];
#pragma unroll
    for (int ks = 0; ks < 4; ks++) {
        int row = w * 16 + l7 + l8 * 8;
        int col = ks * 16 + l16 * 8;
        ldsm4(qa[ks], sptr(&Qs[row][col]));
    }

    float m0 = -1e30f, m1 = -1e30f, l0 = 0.f, l1 = 0.f;
    float o[8][4];
#pragma unroll
    for (int nt = 0; nt < 8; nt++)
#pragma unroll
        for (int r = 0; r < 4; r++) o[nt][r] = 0.f;

    for (int j = 0; j < 32; j++) {
        const int s = j & 1;
        if (j < 31) cp_wait1(); else cp_wait0();
        __syncthreads();

        // ---- S = Q @ K^T ----
        float sc[4][4];
#pragma unroll
        for (int nt = 0; nt < 4; nt++)
#pragma unroll
            for (int r = 0; r < 4; r++) sc[nt][r] = 0.f;
#pragma unroll
        for (int half = 0; half < 2; half++) {
#pragma unroll
            for (int nt = 0; nt < 4; nt++) {
                uint32_t r[4];
                int row = nt * 8 + l7;
                int col = half * 32 + (lane >> 3) * 8;
                ldsm4(r, sptr(&Ks[s][row][col]));
                mma_bf16(sc[nt], qa[half * 2],     r[0], r[1]);
                mma_bf16(sc[nt], qa[half * 2 + 1], r[2], r[3]);
            }
        }

        // ---- online softmax ----
        float mt0 = -1e30f, mt1 = -1e30f;
#pragma unroll
        for (int nt = 0; nt < 4; nt++) {
            mt0 = fmaxf(mt0, fmaxf(sc[nt][0], sc[nt][1]));
            mt1 = fmaxf(mt1, fmaxf(sc[nt][2], sc[nt][3]));
        }
        mt0 = fmaxf(mt0, __shfl_xor_sync(0xffffffffu, mt0, 1));
        mt0 = fmaxf(mt0, __shfl_xor_sync(0xffffffffu, mt0, 2));
        mt1 = fmaxf(mt1, __shfl_xor_sync(0xffffffffu, mt1, 1));
        mt1 = fmaxf(mt1, __shfl_xor_sync(0xffffffffu, mt1, 2));

        float mn0 = fmaxf(m0, mt0), mn1 = fmaxf(m1, mt1);
        float fac0 = __expf(m0 - mn0), fac1 = __expf(m1 - mn1);
        m0 = mn0; m1 = mn1;

        float rs0 = 0.f, rs1 = 0.f;
#pragma unroll
        for (int nt = 0; nt < 4; nt++) {
            sc[nt][0] = __expf(sc[nt][0] - mn0);
            sc[nt][1] = __expf(sc[nt][1] - mn0);
            sc[nt][2] = __expf(sc[nt][2] - mn1);
            sc[nt][3] = __expf(sc[nt][3] - mn1);
            rs0 += sc[nt][0] + sc[nt][1];
            rs1 += sc[nt][2] + sc[nt][3];
        }
        rs0 += __shfl_xor_sync(0xffffffffu, rs0, 1);
        rs0 += __shfl_xor_sync(0xffffffffu, rs0, 2);
        rs1 += __shfl_xor_sync(0xffffffffu, rs1, 1);
        rs1 += __shfl_xor_sync(0xffffffffu, rs1, 2);
        l0 = l0 * fac0 + rs0;
        l1 = l1 * fac1 + rs1;
#pragma unroll
        for (int nt = 0; nt < 8; nt++) {
            o[nt][0] *= fac0; o[nt][1] *= fac0;
            o[nt][2] *= fac1; o[nt][3] *= fac1;
        }

        // ---- O += P @ V ----
#pragma unroll
        for (int ks2 = 0; ks2 < 2; ks2++) {
            uint32_t pa[4];
            pa[0] = packbf(sc[ks2 * 2][0],     sc[ks2 * 2][1]);
            pa[1] = packbf(sc[ks2 * 2][2],     sc[ks2 * 2][3]);
            pa[2] = packbf(sc[ks2 * 2 + 1][0], sc[ks2 * 2 + 1][1]);
            pa[3] = packbf(sc[ks2 * 2 + 1][2], sc[ks2 * 2 + 1][3]);
#pragma unroll
            for (int dp = 0; dp < 4; dp++) {
                uint32_t r[4];
                int row = ks2 * 16 + l7 + l8 * 8;
                int col = dp * 16 + l16 * 8;
                ldsm4t(r, sptr(&Vs[s][row][col]));
                mma_bf16(o[dp * 2],     pa, r[0], r[1]);
                mma_bf16(o[dp * 2 + 1], pa, r[2], r[3]);
            }
        }

        __syncthreads();
        if (j + 2 < 32) {
            int row = tid >> 2;
            int cb  = (tid & 3) * 16;
            const __nv_bfloat16* Kp = K + (size_t)((j + 2) * 32 + row) * 64 + cb;
            const __nv_bfloat16* Vp = V + (size_t)((j + 2) * 32 + row) * 64 + cb;
            cp16(sptr(&Ks[s][row][cb]),     Kp);
            cp16(sptr(&Ks[s][row][cb + 8]), Kp + 8);
            cp16(sptr(&Vs[s][row][cb]),     Vp);
            cp16(sptr(&Vs[s][row][cb + 8]), Vp + 8);
            cp_commit();
        } else {
            cp_commit();
        }
    }

    // epilogue: normalize, store bf16 channel-major [b, h*64+d, n]
    const float inv0 = 1.0f / l0, inv1 = 1.0f / l1;
    __nv_bfloat16* O = g_ao + ((size_t)b * CCH + h * DHEAD) * NTOK;
    const int n0 = it * 64 + w * 16 + g;
#pragma unroll
    for (int nt = 0; nt < 8; nt++) {
        int d = nt * 8 + t * 2;
        O[(size_t)d * NTOK + n0]           = __float2bfloat16(o[nt][0] * inv0);
        O[(size_t)(d + 1) * NTOK + n0]     = __float2bfloat16(o[nt][1] * inv0);
        O[(size_t)d * NTOK + n0 + 8]       = __float2bfloat16(o[nt][2] * inv1);
        O[(size_t)(d + 1) * NTOK + n0 + 8] = __float2bfloat16(o[nt][3] * inv1);
    }
}

// ===========================================================================
// launch
// ===========================================================================
extern "C" void kernel_launch(void* const* d_in, const int* in_sizes, int n_in,
                              void* d_out, int out_size)
{
    const float* x     = (const float*)d_in[0];
    const float* gn_w  = (const float*)d_in[1];
    const float* gn_b  = (const float*)d_in[2];
    const float* w_qkv = (const float*)d_in[3];
    const float* w_prj = (const float*)d_in[4];
    float* out = (float*)d_out;

    __nv_bfloat16* wq_dst; cudaGetSymbolAddress((void**)&wq_dst, g_wqkv);
    __nv_bfloat16* wp_dst; cudaGetSymbolAddress((void**)&wp_dst, g_wproj);

    convert_w_kernel<<<768, 256>>>(w_qkv, wq_dst, 1536 * 512 / 4);
    convert_w_kernel<<<256, 256>>>(w_prj, wp_dst, 512 * 512 / 4);

    groupnorm_kernel<<<BATCH * NGROUP, 256>>>(x, gn_w, gn_b);

    dim3 gq(12, 8, BATCH);
    qkv_gemm_kernel<<<gq, 256>>>();

    dim3 ga(16, NHEADS, BATCH);
    attn_kernel<<<ga, 128>>>();

    dim3 gp(4, 8, BATCH);
    proj_gemm_kernel<<<gp, 256>>>(x, out);
}

// round 5
// speedup vs baseline: 6.6945x; 1.0672x over previous
#include <cuda_runtime.h>
#include <cuda_bf16.h>
#include <math.h>
#include <stdint.h>

#define BATCH   8
#define CCH     512
#define NHEADS  8
#define DHEAD   64
#define NTOK    1024
#define NGROUP  32
#define CPG     16
#define GN_ELEMS (CPG * NTOK)

// ---------------- scratch (alloc-free: __device__ globals) ----------------
__device__ __nv_bfloat16 g_xn[BATCH * CCH * NTOK];            // GN out [b, c, n]
__device__ __nv_bfloat16 g_q [BATCH * NHEADS * NTOK * DHEAD]; // [b,h,n,d], q pre-scaled 1/8
__device__ __nv_bfloat16 g_k [BATCH * NHEADS * NTOK * DHEAD];
__device__ __nv_bfloat16 g_v [BATCH * NHEADS * NTOK * DHEAD];
__device__ __nv_bfloat16 g_ao[BATCH * CCH * NTOK];            // attn out [b, c, n]
__device__ __nv_bfloat16 g_wqkv[1536 * 512];
__device__ __nv_bfloat16 g_wproj[512 * 512];

// ---------------- helpers ----------------
__device__ __forceinline__ uint32_t sptr(const void* p) {
    return (uint32_t)__cvta_generic_to_shared(p);
}
__device__ __forceinline__ void ldsm4(uint32_t r[4], uint32_t addr) {
    asm volatile("ldmatrix.sync.aligned.m8n8.x4.shared.b16 {%0,%1,%2,%3}, [%4];"
                 : "=r"(r[0]), "=r"(r[1]), "=r"(r[2]), "=r"(r[3]) : "r"(addr));
}
__device__ __forceinline__ void ldsm4t(uint32_t r[4], uint32_t addr) {
    asm volatile("ldmatrix.sync.aligned.m8n8.x4.trans.shared.b16 {%0,%1,%2,%3}, [%4];"
                 : "=r"(r[0]), "=r"(r[1]), "=r"(r[2]), "=r"(r[3]) : "r"(addr));
}
__device__ __forceinline__ void mma_bf16(float c[4], const uint32_t a[4],
                                         uint32_t b0, uint32_t b1) {
    asm volatile(
        "mma.sync.aligned.m16n8k16.row.col.f32.bf16.bf16.f32 "
        "{%0,%1,%2,%3},{%4,%5,%6,%7},{%8,%9},{%0,%1,%2,%3};"
        : "+f"(c[0]), "+f"(c[1]), "+f"(c[2]), "+f"(c[3])
        : "r"(a[0]), "r"(a[1]), "r"(a[2]), "r"(a[3]), "r"(b0), "r"(b1));
}
__device__ __forceinline__ uint32_t packbf(float lo, float hi) {
    uint32_t d;
    asm("cvt.rn.bf16x2.f32 %0, %1, %2;" : "=r"(d) : "f"(hi), "f"(lo));
    return d;
}
__device__ __forceinline__ void cp16(uint32_t smem, const void* g) {
    asm volatile("cp.async.ca.shared.global [%0], [%1], 16;" :: "r"(smem), "l"(g));
}
__device__ __forceinline__ void cp_commit() { asm volatile("cp.async.commit_group;"); }
__device__ __forceinline__ void cp_wait1()  { asm volatile("cp.async.wait_group 1;"); }
__device__ __forceinline__ void cp_wait0()  { asm volatile("cp.async.wait_group 0;"); }

// ===========================================================================
// Kernel 0: convert fp32 weights -> bf16
// ===========================================================================
__global__ void __launch_bounds__(256) convert_w_kernel(
    const float* __restrict__ src, __nv_bfloat16* __restrict__ dst, int n4)
{
    int i = blockIdx.x * 256 + threadIdx.x;
    if (i >= n4) return;
    float4 v = *(const float4*)(src + (size_t)i * 4);
    *(uint2*)(dst + (size_t)i * 4) = make_uint2(packbf(v.x, v.y), packbf(v.z, v.w));
}

// ===========================================================================
// Kernel 1: GroupNorm -> bf16 channel-major [b, c, n].
// ===========================================================================
__global__ void __launch_bounds__(256) groupnorm_kernel(
    const float* __restrict__ x,
    const float* __restrict__ gw,
    const float* __restrict__ gb)
{
    const int b = blockIdx.x >> 5;
    const int g = blockIdx.x & 31;
    const int tid = threadIdx.x;
    const float* xp = x + ((size_t)b * CCH + g * CPG) * NTOK;

    float s = 0.f, ss = 0.f;
    for (int i = tid * 2; i < GN_ELEMS; i += 512) {
        float2 v = *(const float2*)(xp + i);
        s += v.x + v.y;
        ss += v.x * v.x + v.y * v.y;
    }
    __shared__ float shs[256];
    __shared__ float shq[256];
    shs[tid] = s; shq[tid] = ss;
    __syncthreads();
    for (int o = 128; o > 0; o >>= 1) {
        if (tid < o) { shs[tid] += shs[tid + o]; shq[tid] += shq[tid + o]; }
        __syncthreads();
    }
    const float mean = shs[0] * (1.0f / (float)GN_ELEMS);
    const float var  = shq[0] * (1.0f / (float)GN_ELEMS) - mean * mean;
    const float rstd = rsqrtf(var + 1e-5f);

    uint32_t* op = (uint32_t*)(g_xn + ((size_t)b * CCH + g * CPG) * NTOK);
    for (int i = tid * 2; i < GN_ELEMS; i += 512) {
        int c = g * CPG + (i >> 10);
        float2 v = *(const float2*)(xp + i);
        float a0 = (v.x - mean) * rstd * gw[c] + gb[c];
        float a1 = (v.y - mean) * rstd * gw[c] + gb[c];
        op[i >> 1] = packbf(a0, a1);
    }
}

// ===========================================================================
// bf16 GEMM core: CTA tile 128x128 of W[M,512] @ B[512,1024].
// 4 warps (2x2), warp tile 64x64, BK=32, cp.async 2-stage, 128 threads.
// ===========================================================================
#define APAD 40
#define BPAD 136

struct GemmCtx { float acc[4][8][4]; int g, t, wm, wn; };

__device__ __forceinline__ void gemm_main_bf16(
    const __nv_bfloat16* __restrict__ Wbf,     // [M,512]
    const __nv_bfloat16* __restrict__ Xbf,     // [512,1024]
    int bm, int bn, GemmCtx& ctx)
{
    __shared__ __align__(16) __nv_bfloat16 As[2][128][APAD];
    __shared__ __align__(16) __nv_bfloat16 Bs[2][32][BPAD];

    const int tid = threadIdx.x;
    const int lane = tid & 31;
    const int warpid = tid >> 5;
    ctx.g = lane >> 2;
    ctx.t = lane & 3;
    ctx.wm = (warpid >> 1) * 64;
    ctx.wn = (warpid & 1) * 64;

#pragma unroll
    for (int mt = 0; mt < 4; mt++)
#pragma unroll
        for (int nt = 0; nt < 8; nt++)
#pragma unroll
            for (int r = 0; r < 4; r++) ctx.acc[mt][nt][r] = 0.f;

    // cp.async fill indices: A 512 chunks, B 512 chunks of 16B, 4 each per thread
#define GEMM_FILL(stage, k0) do { \
    _Pragma("unroll") \
    for (int i = 0; i < 4; i++) { \
        int idx = tid + i * 128; \
        int row = idx >> 2, q = idx & 3; \
        cp16(sptr(&As[stage][row][q * 8]), Wbf + (size_t)(bm + row) * 512 + (k0) + q * 8); \
    } \
    _Pragma("unroll") \
    for (int i = 0; i < 4; i++) { \
        int idx = tid + i * 128; \
        int row = idx >> 4, sg = idx & 15; \
        cp16(sptr(&Bs[stage][row][sg * 8]), Xbf + (size_t)((k0) + row) * NTOK + bn + sg * 8); \
    } \
} while (0)

    GEMM_FILL(0, 0);
    cp_commit();
    GEMM_FILL(1, 32);
    cp_commit();

    const int l7 = lane & 7, l8 = (lane >> 3) & 1, l16 = lane >> 4;

    for (int kc = 0; kc < 16; kc++) {
        const int s = kc & 1;
        if (kc < 15) cp_wait1(); else cp_wait0();
        __syncthreads();

#pragma unroll
        for (int kk = 0; kk < 32; kk += 16) {
            uint32_t a[4][4], bb[8][2];
#pragma unroll
            for (int mt = 0; mt < 4; mt++) {
                int row = ctx.wm + mt * 16 + l7 + l8 * 8;
                int col = kk + l16 * 8;
                ldsm4(a[mt], sptr(&As[s][row][col]));
            }
#pragma unroll
            for (int np = 0; np < 4; np++) {
                int row = kk + l7 + l8 * 8;
                int col = ctx.wn + np * 16 + l16 * 8;
                uint32_t r[4];
                ldsm4t(r, sptr(&Bs[s][row][col]));
                bb[np * 2][0] = r[0]; bb[np * 2][1] = r[1];
                bb[np * 2 + 1][0] = r[2]; bb[np * 2 + 1][1] = r[3];
            }
#pragma unroll
            for (int mt = 0; mt < 4; mt++)
#pragma unroll
                for (int nt = 0; nt < 8; nt++)
                    mma_bf16(ctx.acc[mt][nt], a[mt], bb[nt][0], bb[nt][1]);
        }
        __syncthreads();
        if (kc + 2 < 16) {
            GEMM_FILL(s, (kc + 2) * 32);
        }
        cp_commit();   // keep group count consistent
    }
#undef GEMM_FILL
}

// ---- QKV GEMM -> g_q/g_k/g_v [b,h,n,d] bf16. grid (12, 8, 8), 128 thr ----
__global__ void __launch_bounds__(128) qkv_gemm_kernel()
{
    const int b  = blockIdx.z;
    const int bm = blockIdx.x * 128;
    const int bn = blockIdx.y * 128;
    const __nv_bfloat16* X = g_xn + (size_t)b * CCH * NTOK;

    GemmCtx ctx;
    gemm_main_bf16(g_wqkv, X, bm, bn, ctx);

    const int which = bm >> 9;
    __nv_bfloat16* dst = (which == 0) ? g_q : ((which == 1) ? g_k : g_v);
    const float qs = (which == 0) ? 0.125f : 1.0f;

#pragma unroll
    for (int mt = 0; mt < 4; mt++) {
#pragma unroll
        for (int rr = 0; rr < 2; rr++) {
            int o  = (bm & 511) + ctx.wm + mt * 16 + ctx.g + rr * 8;
            int h  = o >> 6;
            int dd = o & 63;
            __nv_bfloat16* row = dst + (((size_t)b * NHEADS + h) * NTOK) * DHEAD + dd;
#pragma unroll
            for (int nt = 0; nt < 8; nt++) {
                int n = bn + ctx.wn + nt * 8 + ctx.t * 2;
                row[(size_t)n * DHEAD]       = __float2bfloat16(ctx.acc[mt][nt][rr * 2 + 0] * qs);
                row[(size_t)(n + 1) * DHEAD] = __float2bfloat16(ctx.acc[mt][nt][rr * 2 + 1] * qs);
            }
        }
    }
}

// ---- proj GEMM + residual -> out fp32. grid (4, 8, 8), 128 thr ----
__global__ void __launch_bounds__(128) proj_gemm_kernel(
    const float* __restrict__ x, float* __restrict__ out)
{
    const int b  = blockIdx.z;
    const int bm = blockIdx.x * 128;
    const int bn = blockIdx.y * 128;
    const __nv_bfloat16* AO = g_ao + (size_t)b * CCH * NTOK;

    GemmCtx ctx;
    gemm_main_bf16(g_wproj, AO, bm, bn, ctx);

#pragma unroll
    for (int mt = 0; mt < 4; mt++) {
#pragma unroll
        for (int rr = 0; rr < 2; rr++) {
            int o = bm + ctx.wm + mt * 16 + ctx.g + rr * 8;
            const float* xr  = x   + ((size_t)b * CCH + o) * NTOK;
            float*       orw = out + ((size_t)b * CCH + o) * NTOK;
#pragma unroll
            for (int nt = 0; nt < 8; nt++) {
                int n = bn + ctx.wn + nt * 8 + ctx.t * 2;
                orw[n]     = xr[n]     + ctx.acc[mt][nt][rr * 2 + 0];
                orw[n + 1] = xr[n + 1] + ctx.acc[mt][nt][rr * 2 + 1];
            }
        }
    }
}

// ===========================================================================
// Kernel 3: flash attention, bf16 MMA + ldmatrix, 32 q-rows per warp.
// grid = (8, 8, 8), 128 threads (4 warps, CTA = 128 q-rows). j-tile = 32.
// Each K/V fragment feeds 2 m-tiles -> half the LDSM per FLOP vs R3.
// ===========================================================================
#define KVPAD 72

__global__ void __launch_bounds__(128) attn_kernel()
{
    const int it = blockIdx.x;
    const int h  = blockIdx.y;
    const int b  = blockIdx.z;
    const size_t base = (((size_t)b * NHEADS + h) * NTOK) * DHEAD;
    const __nv_bfloat16* Q = g_q + base;
    const __nv_bfloat16* K = g_k + base;
    const __nv_bfloat16* V = g_v + base;

    __shared__ __align__(16) __nv_bfloat16 Qs[128][KVPAD];
    __shared__ __align__(16) __nv_bfloat16 Ks[2][32][KVPAD];
    __shared__ __align__(16) __nv_bfloat16 Vs[2][32][KVPAD];

    const int tid  = threadIdx.x;
    const int lane = tid & 31;
    const int w    = tid >> 5;
    const int g    = lane >> 2;
    const int t    = lane & 3;
    const int l7 = lane & 7, l8 = (lane >> 3) & 1, l16 = lane >> 4;

    // stage Q tile (128 x 64): one row per thread
    {
        const __nv_bfloat16* Qr = Q + (size_t)(it * 128 + tid) * 64;
#pragma unroll
        for (int q = 0; q < 8; q++)
            *(uint4*)&Qs[tid][q * 8] = *(const uint4*)(Qr + q * 8);
    }
    // prologue KV: stage tiles 0,1
    {
        int row = tid >> 2;
        int cb  = (tid & 3) * 16;
#pragma unroll
        for (int jc = 0; jc < 2; jc++) {
            const __nv_bfloat16* Kp = K + (size_t)(jc * 32 + row) * 64 + cb;
            const __nv_bfloat16* Vp = V + (size_t)(jc * 32 + row) * 64 + cb;
            cp16(sptr(&Ks[jc][row][cb]),     Kp);
            cp16(sptr(&Ks[jc][row][cb + 8]), Kp + 8);
            cp16(sptr(&Vs[jc][row][cb]),     Vp);
            cp16(sptr(&Vs[jc][row][cb + 8]), Vp + 8);
            cp_commit();
        }
    }
    __syncthreads();

    // preload Q fragments: qa[mt][ks][4], mt = m-tile (16 rows), ks = d/16
    uint32_t qa[2][4][4];
#pragma unroll
    for (int mt = 0; mt < 2; mt++)
#pragma unroll
        for (int ks = 0; ks < 4; ks++) {
            int row = w * 32 + mt * 16 + l7 + l8 * 8;
            int col = ks * 16 + l16 * 8;
            ldsm4(qa[mt][ks], sptr(&Qs[row][col]));
        }

    float m[2][2], l[2][2];
    float o[2][8][4];
#pragma unroll
    for (int mt = 0; mt < 2; mt++) {
        m[mt][0] = -1e30f; m[mt][1] = -1e30f;
        l[mt][0] = 0.f;    l[mt][1] = 0.f;
#pragma unroll
        for (int nt = 0; nt < 8; nt++)
#pragma unroll
            for (int r = 0; r < 4; r++) o[mt][nt][r] = 0.f;
    }

    for (int j = 0; j < 32; j++) {
        const int s = j & 1;
        if (j < 31) cp_wait1(); else cp_wait0();
        __syncthreads();

        // ---- S = Q @ K^T ----
        float sc[2][4][4];
#pragma unroll
        for (int mt = 0; mt < 2; mt++)
#pragma unroll
            for (int nt = 0; nt < 4; nt++)
#pragma unroll
                for (int r = 0; r < 4; r++) sc[mt][nt][r] = 0.f;
#pragma unroll
        for (int half = 0; half < 2; half++) {
#pragma unroll
            for (int nt = 0; nt < 4; nt++) {
                uint32_t r[4];
                int row = nt * 8 + l7;
                int col = half * 32 + (lane >> 3) * 8;
                ldsm4(r, sptr(&Ks[s][row][col]));
#pragma unroll
                for (int mt = 0; mt < 2; mt++) {
                    mma_bf16(sc[mt][nt], qa[mt][half * 2],     r[0], r[1]);
                    mma_bf16(sc[mt][nt], qa[mt][half * 2 + 1], r[2], r[3]);
                }
            }
        }

        // ---- online softmax per m-tile ----
        float fac[2][2];
#pragma unroll
        for (int mt = 0; mt < 2; mt++) {
            float mt0 = -1e30f, mt1 = -1e30f;
#pragma unroll
            for (int nt = 0; nt < 4; nt++) {
                mt0 = fmaxf(mt0, fmaxf(sc[mt][nt][0], sc[mt][nt][1]));
                mt1 = fmaxf(mt1, fmaxf(sc[mt][nt][2], sc[mt][nt][3]));
            }
            mt0 = fmaxf(mt0, __shfl_xor_sync(0xffffffffu, mt0, 1));
            mt0 = fmaxf(mt0, __shfl_xor_sync(0xffffffffu, mt0, 2));
            mt1 = fmaxf(mt1, __shfl_xor_sync(0xffffffffu, mt1, 1));
            mt1 = fmaxf(mt1, __shfl_xor_sync(0xffffffffu, mt1, 2));

            float mn0 = fmaxf(m[mt][0], mt0), mn1 = fmaxf(m[mt][1], mt1);
            fac[mt][0] = __expf(m[mt][0] - mn0);
            fac[mt][1] = __expf(m[mt][1] - mn1);
            m[mt][0] = mn0; m[mt][1] = mn1;

            float rs0 = 0.f, rs1 = 0.f;
#pragma unroll
            for (int nt = 0; nt < 4; nt++) {
                sc[mt][nt][0] = __expf(sc[mt][nt][0] - mn0);
                sc[mt][nt][1] = __expf(sc[mt][nt][1] - mn0);
                sc[mt][nt][2] = __expf(sc[mt][nt][2] - mn1);
                sc[mt][nt][3] = __expf(sc[mt][nt][3] - mn1);
                rs0 += sc[mt][nt][0] + sc[mt][nt][1];
                rs1 += sc[mt][nt][2] + sc[mt][nt][3];
            }
            rs0 += __shfl_xor_sync(0xffffffffu, rs0, 1);
            rs0 += __shfl_xor_sync(0xffffffffu, rs0, 2);
            rs1 += __shfl_xor_sync(0xffffffffu, rs1, 1);
            rs1 += __shfl_xor_sync(0xffffffffu, rs1, 2);
            l[mt][0] = l[mt][0] * fac[mt][0] + rs0;
            l[mt][1] = l[mt][1] * fac[mt][1] + rs1;
#pragma unroll
            for (int nt = 0; nt < 8; nt++) {
                o[mt][nt][0] *= fac[mt][0]; o[mt][nt][1] *= fac[mt][0];
                o[mt][nt][2] *= fac[mt][1]; o[mt][nt][3] *= fac[mt][1];
            }
        }

        // ---- O += P @ V ----
#pragma unroll
        for (int ks2 = 0; ks2 < 2; ks2++) {
            uint32_t pa[2][4];
#pragma unroll
            for (int mt = 0; mt < 2; mt++) {
                pa[mt][0] = packbf(sc[mt][ks2 * 2][0],     sc[mt][ks2 * 2][1]);
                pa[mt][1] = packbf(sc[mt][ks2 * 2][2],     sc[mt][ks2 * 2][3]);
                pa[mt][2] = packbf(sc[mt][ks2 * 2 + 1][0], sc[mt][ks2 * 2 + 1][1]);
                pa[mt][3] = packbf(sc[mt][ks2 * 2 + 1][2], sc[mt][ks2 * 2 + 1][3]);
            }
#pragma unroll
            for (int dp = 0; dp < 4; dp++) {
                uint32_t r[4];
                int row = ks2 * 16 + l7 + l8 * 8;
                int col = dp * 16 + l16 * 8;
                ldsm4t(r, sptr(&Vs[s][row][col]));
#pragma unroll
                for (int mt = 0; mt < 2; mt++) {
                    mma_bf16(o[mt][dp * 2],     pa[mt], r[0], r[1]);
                    mma_bf16(o[mt][dp * 2 + 1], pa[mt], r[2], r[3]);
                }
            }
        }

        __syncthreads();
        if (j + 2 < 32) {
            int row = tid >> 2;
            int cb  = (tid & 3) * 16;
            const __nv_bfloat16* Kp = K + (size_t)((j + 2) * 32 + row) * 64 + cb;
            const __nv_bfloat16* Vp = V + (size_t)((j + 2) * 32 + row) * 64 + cb;
            cp16(sptr(&Ks[s][row][cb]),     Kp);
            cp16(sptr(&Ks[s][row][cb + 8]), Kp + 8);
            cp16(sptr(&Vs[s][row][cb]),     Vp);
            cp16(sptr(&Vs[s][row][cb + 8]), Vp + 8);
            cp_commit();
        } else {
            cp_commit();
        }
    }

    // epilogue: normalize, store bf16 channel-major [b, h*64+d, n]
    __nv_bfloat16* O = g_ao + ((size_t)b * CCH + h * DHEAD) * NTOK;
#pragma unroll
    for (int mt = 0; mt < 2; mt++) {
        const float inv0 = 1.0f / l[mt][0], inv1 = 1.0f / l[mt][1];
        const int n0 = it * 128 + w * 32 + mt * 16 + g;
#pragma unroll
        for (int nt = 0; nt < 8; nt++) {
            int d = nt * 8 + t * 2;
            O[(size_t)d * NTOK + n0]           = __float2bfloat16(o[mt][nt][0] * inv0);
            O[(size_t)(d + 1) * NTOK + n0]     = __float2bfloat16(o[mt][nt][1] * inv0);
            O[(size_t)d * NTOK + n0 + 8]       = __float2bfloat16(o[mt][nt][2] * inv1);
            O[(size_t)(d + 1) * NTOK + n0 + 8] = __float2bfloat16(o[mt][nt][3] * inv1);
        }
    }
}

// ===========================================================================
// launch
// ===========================================================================
extern "C" void kernel_launch(void* const* d_in, const int* in_sizes, int n_in,
                              void* d_out, int out_size)
{
    (void)in_sizes; (void)n_in; (void)out_size;
    const float* x     = (const float*)d_in[0];
    const float* gn_w  = (const float*)d_in[1];
    const float* gn_b  = (const float*)d_in[2];
    const float* w_qkv = (const float*)d_in[3];
    const float* w_prj = (const float*)d_in[4];
    float* out = (float*)d_out;

    __nv_bfloat16* wq_dst; cudaGetSymbolAddress((void**)&wq_dst, g_wqkv);
    __nv_bfloat16* wp_dst; cudaGetSymbolAddress((void**)&wp_dst, g_wproj);

    convert_w_kernel<<<768, 256>>>(w_qkv, wq_dst, 1536 * 512 / 4);
    convert_w_kernel<<<256, 256>>>(w_prj, wp_dst, 512 * 512 / 4);

    groupnorm_kernel<<<BATCH * NGROUP, 256>>>(x, gn_w, gn_b);

    dim3 gq(12, 8, BATCH);
    qkv_gemm_kernel<<<gq, 128>>>();

    dim3 ga(8, NHEADS, BATCH);
    attn_kernel<<<ga, 128>>>();

    dim3 gp(4, 8, BATCH);
    proj_gemm_kernel<<<gp, 128>>>(x, out);
}